// round 17
// baseline (speedup 1.0000x reference)
#include <cuda_runtime.h>
#include <cstdint>

#define FFTC 256
#define NL 11
#define TT 2048
#define NCTA 8
#define SPS 12                       // stages/step: s=0..10 layer partials; s=11 logits partials
#define NSL 12                       // mbarrier slots (parity handles step reuse)
#define NFLAGS (TT*SPS)
#define FSTRIDE 32                   // one 128B L2 line per flag (fallback fabric)
#define MEMCOLS 2047                 // sum of dilations 1+2+...+1024

// Persistent state (recomputed every kernel_launch for determinism)
__device__ float g_ring[(size_t)NCTA*MEMCOLS*FFTC]; // PRIVATE ring buffer per CTA
__device__ float g_cond[NL*16*FFTC];                // cond projections per (layer, frame)
__device__ float g_emb[256*FFTC];                   // tanh(emb_raw)
__device__ float g_part[12*NCTA*FFTC];              // per-layer (+logits) partial z vectors
__device__ unsigned g_flags[(size_t)NFLAGS*FSTRIDE];// fallback: monotone per-stage counters

// ---- fallback (R12) fabric ----
__device__ __forceinline__ void poll_flag(int s, unsigned expect){
  const unsigned* p = g_flags + (size_t)s*FSTRIDE;
  unsigned v;
  do {
    asm volatile("ld.acquire.gpu.global.u32 %0, [%1];" : "=r"(v) : "l"(p) : "memory");
  } while (v < expect);
}
__device__ __forceinline__ void release_flag(int s){
  asm volatile("red.release.gpu.global.add.u32 [%0], %1;"
               :: "l"(g_flags + (size_t)s*FSTRIDE), "r"(1u) : "memory");
}

// ---- cluster mbarrier fabric ----
__device__ __forceinline__ uint32_t smem_u32(const void* p){
  uint32_t a;
  asm("{ .reg .u64 t; cvta.to.shared.u64 t, %1; cvt.u32.u64 %0, t; }" : "=r"(a) : "l"(p));
  return a;
}
__device__ __forceinline__ uint32_t mapa32(uint32_t addr, uint32_t rank){
  uint32_t r; asm("mapa.shared::cluster.u32 %0, %1, %2;" : "=r"(r) : "r"(addr), "r"(rank));
  return r;
}
__device__ __forceinline__ void mb_init(uint32_t bar, uint32_t count){
  asm volatile("mbarrier.init.shared.b64 [%0], %1;" :: "r"(bar), "r"(count) : "memory");
}
__device__ __forceinline__ void mb_arrive_remote(uint32_t bar){
  asm volatile("mbarrier.arrive.release.cluster.shared::cluster.b64 _, [%0];"
               :: "r"(bar) : "memory");
}
__device__ __forceinline__ void mb_wait(uint32_t bar, uint32_t parity){
  uint32_t done;
  asm volatile("{\n\t.reg .pred P;\n\t"
    "mbarrier.try_wait.parity.acquire.cluster.shared::cta.b64 P, [%1], %2;\n\t"
    "selp.b32 %0, 1, 0, P;\n\t}"
    : "=r"(done) : "r"(bar), "r"(parity) : "memory");
  while (!done){
    asm volatile("{\n\t.reg .pred P;\n\t"
      "mbarrier.try_wait.parity.acquire.cluster.shared::cta.b64 P, [%1], %2, 0x989680;\n\t"
      "selp.b32 %0, 1, 0, P;\n\t}"
      : "=r"(done) : "r"(bar), "r"(parity) : "memory");
  }
}
__device__ __forceinline__ void cluster_sync_all(){
  asm volatile("barrier.cluster.arrive.aligned;" ::: "memory");
  asm volatile("barrier.cluster.wait.aligned;"   ::: "memory");
}

// 8-float (32B) weight load: read-only, keep resident in L2 (evict_last).
struct F8 { float f[8]; };
__device__ __forceinline__ F8 ldnc8(const float* p){
  unsigned long long a,b,c,d;
  asm volatile("ld.global.nc.L2::evict_last.v4.b64 {%0,%1,%2,%3}, [%4];"
               : "=l"(a), "=l"(b), "=l"(c), "=l"(d) : "l"(p));
  F8 r;
  r.f[0] = __uint_as_float((unsigned)(a));        r.f[1] = __uint_as_float((unsigned)(a>>32));
  r.f[2] = __uint_as_float((unsigned)(b));        r.f[3] = __uint_as_float((unsigned)(b>>32));
  r.f[4] = __uint_as_float((unsigned)(c));        r.f[5] = __uint_as_float((unsigned)(c>>32));
  r.f[6] = __uint_as_float((unsigned)(d));        r.f[7] = __uint_as_float((unsigned)(d>>32));
  return r;
}
__device__ __forceinline__ float ldcg(const float* p){
  float v;
  asm volatile("ld.global.cg.f32 %0, [%1];" : "=f"(v) : "l"(p));
  return v;
}

__device__ __forceinline__ float dot8(const F8& w, const float* v, float p){
  #pragma unroll
  for (int k=0;k<8;k++) p = fmaf(w.f[k], v[k], p);
  return p;
}

// ---------------- init + precompute fused ----------------
__global__ void init_all(const float* __restrict__ y,
                         const float* __restrict__ emb_raw,
                         const float* __restrict__ condW){
  const int b = blockIdx.x, tid = threadIdx.x;
  if (b < 256) {
    g_emb[b*256 + tid] = tanhf(emb_raw[b*256 + tid]);
  } else if (b < 256 + NL*16) {
    int b2 = b - 256;
    int j = b2 >> 4, f = b2 & 15;
    int row = j*256 + tid;
    float acc = 0.0f;
    #pragma unroll
    for (int c=0; c<80; c++) acc = fmaf(condW[row*80 + c], y[c*16 + f], acc);
    g_cond[(j*16 + f)*256 + tid] = acc;
  }
  size_t i = (size_t)b*blockDim.x + tid;
  size_t stride = (size_t)gridDim.x*blockDim.x;
  for (size_t k=i; k<(size_t)NCTA*MEMCOLS*FFTC; k+=stride) g_ring[k] = 0.0f;
  for (size_t k=i; k<(size_t)NFLAGS*FSTRIDE; k+=stride) g_flags[k] = 0u;
}

// ---------------- shared body: 8 CTAs x 512 threads ----------------
// Stage A: warp w owns TWO h-rows: r0 = blk*32+w, r1 = blk*32+16+w (two
// independent accumulator chains; dual shfl-reduce).
// Partial z: zrow = tid>>1 (256 outputs), half = tid&1; this CTA's 32-wide
// inner slice, thread covers 16 (2x dot8) then pair-shfl.
// One chip-wide sync per layer; x', logits, SAMPLER computed redundantly per CTA.
template<bool MB>
__device__ __forceinline__ void fftnet_body(
  const float* __restrict__ WVp, const float* __restrict__ WVc,
  const float* __restrict__ Wow, const float* __restrict__ Wob,
  const float* __restrict__ endw, const float* __restrict__ endb,
  const float* __restrict__ samples, float* __restrict__ out)
{
  __shared__ __align__(16) float xs[FFTC];   // current x (identical in all CTAs)
  __shared__ __align__(16) float hs[32];     // this CTA's h rows
  __shared__ __align__(16) float lg[FFTC];   // logits (all CTAs)
  __shared__ __align__(16) float es[FFTC];   // staged emb row (sampler)
  __shared__ __align__(8) unsigned long long bars[NSL];
  __shared__ int s_sel;
  const int tid = threadIdx.x;
  const int blk = blockIdx.x;
  const int w = tid >> 5, lane = tid & 31;
  const int r0 = blk*32 + w;                 // first h row owned by this warp
  const int r1 = r0 + 16;                    // second h row
  const int zrow = tid >> 1;
  const int half = tid & 1;
  const int hb = half*16;                    // local h base for partial z
  const int in0 = blk*32 + hb;               // global inner base for partial z
  float* ring = g_ring + (size_t)blk*MEMCOLS*FFTC;

  uint32_t bar_u = 0, peer_bar = 0;
  if (MB){
    bar_u = smem_u32(bars);
    if (tid == 0){
      #pragma unroll
      for (int s=0;s<NSL;s++) mb_init(bar_u + s*8, NCTA);
    }
    __syncthreads();
    cluster_sync_all();                      // all slots initialized cluster-wide
    if (tid < NCTA) peer_bar = mapa32(bar_u, (uint32_t)tid);
  }

  if (tid < FFTC) xs[tid] = g_emb[127*FFTC + tid];
  __syncthreads();

  for (int t=0; t<TT; ++t){
    const int f = t >> 7;
    const int base = t*SPS;
    const uint32_t par = (uint32_t)(t & 1);

    #pragma unroll 1
    for (int j=0; j<NL; ++j){
      const int col = ((1<<j) - 1) + (t & ((1<<j) - 1));
      // ---- issue loads; compute x-independent terms pre-wait ----
      F8 wp0 = ldnc8(WVp + (size_t)(j*FFTC + r0)*FFTC + lane*8);
      F8 wp1 = ldnc8(WVp + (size_t)(j*FFTC + r1)*FFTC + lane*8);
      float mc[8];
      *(float4*)(mc)   = *(const float4*)(ring + col*FFTC + lane*8);
      *(float4*)(mc+4) = *(const float4*)(ring + col*FFTC + lane*8 + 4);
      F8 wc0 = ldnc8(WVc + (size_t)(j*FFTC + r0)*FFTC + lane*8);
      F8 wc1 = ldnc8(WVc + (size_t)(j*FFTC + r1)*FFTC + lane*8);
      F8 woa = ldnc8(Wow + (size_t)(j*FFTC + zrow)*FFTC + in0);
      F8 wob = ldnc8(Wow + (size_t)(j*FFTC + zrow)*FFTC + in0 + 8);
      float cnd0 = (lane==0) ? g_cond[(j*16 + f)*FFTC + r0] : 0.0f;
      float cnd1 = (lane==0) ? g_cond[(j*16 + f)*FFTC + r1] : 0.0f;
      float wobp = (j>0 && tid<FFTC) ? Wob[(j-1)*FFTC + tid] : 0.0f;
      float part0 = dot8(wp0, mc, cnd0);     // past-tap dots: pre-wait
      float part1 = dot8(wp1, mc, cnd1);

      if (j > 0){
        if (MB) { mb_wait(bar_u + (j-1)*8, par); }
        else    { if (tid==0) poll_flag(base + (j-1), NCTA); __syncthreads(); }
        if (tid < FFTC){
          float s1 = wobp;
          const float* gp = g_part + (j-1)*NCTA*FFTC + tid;
          #pragma unroll
          for (int k=0;k<NCTA;k++) s1 += ldcg(gp + k*FFTC);
          xs[tid] = fmaxf(s1 + xs[tid], 0.0f);        // x' = relu(z + b + x)
        }
        __syncthreads();
      }
      part0 = dot8(wc0, xs + lane*8, part0);
      part1 = dot8(wc1, xs + lane*8, part1);
      #pragma unroll
      for (int k=16;k>0;k>>=1){
        part0 += __shfl_xor_sync(0xffffffffu, part0, k);
        part1 += __shfl_xor_sync(0xffffffffu, part1, k);
      }
      if (lane==0){ hs[w] = fmaxf(part0, 0.0f); hs[16+w] = fmaxf(part1, 0.0f); }
      __syncthreads();
      // partial z over this CTA's 32 h rows (16 per thread, pair-shfl)
      float pk = dot8(woa, hs + hb, 0.0f);
      pk = dot8(wob, hs + hb + 8, pk);
      float oth = __shfl_xor_sync(0xffffffffu, pk, 1);
      float z = (half==0) ? (pk + oth) : (oth + pk);
      if (half==0) g_part[(j*NCTA + blk)*FFTC + zrow] = z;
      __syncthreads();                                // partial stores before publish
      if (MB) { if (tid < NCTA) mb_arrive_remote(peer_bar + j*8); }
      else    { if (tid==0) release_flag(base + j); }
      if (tid < FFTC) ring[col*FFTC + tid] = xs[tid]; // private, off the publish path
    }

    { // ---- logits: x' after layer 10, then partial endw slice ----
      F8 ewa = ldnc8(endw + (size_t)zrow*FFTC + in0);
      F8 ewb = ldnc8(endw + (size_t)zrow*FFTC + in0 + 8);
      float wobL = (tid<FFTC) ? Wob[10*FFTC + tid] : 0.0f;
      if (MB) { mb_wait(bar_u + 10*8, par); }
      else    { if (tid==0) poll_flag(base + 10, NCTA); __syncthreads(); }
      if (tid < FFTC){
        float s1 = wobL;
        const float* gp = g_part + 10*NCTA*FFTC + tid;
        #pragma unroll
        for (int k=0;k<NCTA;k++) s1 += ldcg(gp + k*FFTC);
        xs[tid] = fmaxf(s1 + xs[tid], 0.0f);
      }
      __syncthreads();
      float pk = dot8(ewa, xs + in0, 0.0f);
      pk = dot8(ewb, xs + in0 + 8, pk);
      float oth = __shfl_xor_sync(0xffffffffu, pk, 1);
      float z = (half==0) ? (pk + oth) : (oth + pk);
      if (half==0) g_part[(11*NCTA + blk)*FFTC + zrow] = z;
      __syncthreads();
      if (MB) { if (tid < NCTA) mb_arrive_remote(peer_bar + 11*8); }
      else    { if (tid==0) release_flag(base + 11); }
    }

    { // ---- sampler: ALL CTAs redundantly (deterministic) ----
      float u = (tid < 32) ? samples[t] : 0.0f;
      if (MB) { mb_wait(bar_u + 11*8, par); }
      else    { if (tid==0) poll_flag(base + 11, NCTA); __syncthreads(); }
      if (tid < FFTC){
        float s1 = endb[tid];
        const float* gp = g_part + 11*NCTA*FFTC + tid;
        #pragma unroll
        for (int k=0;k<NCTA;k++) s1 += ldcg(gp + k*FFTC);
        lg[tid] = s1;                                 // C_SCALE == 1
      }
      __syncthreads();
      if (tid < 32){
        float4 va = *(const float4*)(lg + lane*8);
        float4 vb = *(const float4*)(lg + lane*8 + 4);
        float v[8] = {va.x,va.y,va.z,va.w,vb.x,vb.y,vb.z,vb.w};
        float m = v[0];
        #pragma unroll
        for (int k=1;k<8;k++) m = fmaxf(m, v[k]);
        #pragma unroll
        for (int k=16;k>0;k>>=1) m = fmaxf(m, __shfl_xor_sync(0xffffffffu, m, k));
        float e[8]; float sl = 0.0f;
        #pragma unroll
        for (int k=0;k<8;k++){ e[k] = expf(v[k] - m); sl += e[k]; }
        float tot = sl;
        #pragma unroll
        for (int k=16;k>0;k>>=1) tot += __shfl_xor_sync(0xffffffffu, tot, k);
        float cs[8]; float c = 0.0f;
        #pragma unroll
        for (int k=0;k<8;k++){ c += e[k] / tot; cs[k] = c; }
        float inc = c;
        #pragma unroll
        for (int k=1;k<32;k<<=1){ float o = __shfl_up_sync(0xffffffffu, inc, k); if (lane>=k) inc += o; }
        float off = __shfl_up_sync(0xffffffffu, inc, 1);
        if (lane == 0) off = 0.0f;
        int cand = 1<<30;
        #pragma unroll
        for (int k=0;k<8;k++) if (cand == (1<<30) && (off + cs[k]) > u) cand = lane*8 + k;
        #pragma unroll
        for (int k=16;k>0;k>>=1) cand = min(cand, __shfl_xor_sync(0xffffffffu, cand, k));
        int sel = (cand >= 256) ? 0 : cand;
        if (lane == 0){
          s_sel = sel;
          if (blk == 0) out[t] = (float)sel;
        }
        F8 er = ldnc8(g_emb + sel*FFTC + lane*8);
        #pragma unroll
        for (int k=0;k<8;k++) es[lane*8 + k] = er.f[k];
      }
      __syncthreads();
      if (tid < FFTC) xs[tid] = es[tid];              // next step's x0, locally
      __syncthreads();
    }
  }

  if (MB) cluster_sync_all();  // no CTA exits with peers' remote arrives in flight
}

__global__ void __cluster_dims__(NCTA,1,1) __launch_bounds__(512,1) fftnet_mbar(
  const float* __restrict__ WVp, const float* __restrict__ WVc,
  const float* __restrict__ Wow, const float* __restrict__ Wob,
  const float* __restrict__ endw, const float* __restrict__ endb,
  const float* __restrict__ samples, float* __restrict__ out)
{ fftnet_body<true>(WVp, WVc, Wow, Wob, endw, endb, samples, out); }

__global__ void __launch_bounds__(512,1) fftnet_flags(
  const float* __restrict__ WVp, const float* __restrict__ WVc,
  const float* __restrict__ Wow, const float* __restrict__ Wob,
  const float* __restrict__ endw, const float* __restrict__ endb,
  const float* __restrict__ samples, float* __restrict__ out)
{ fftnet_body<false>(WVp, WVc, Wow, Wob, endw, endb, samples, out); }

extern "C" void kernel_launch(void* const* d_in, const int* in_sizes, int n_in,
                              void* d_out, int out_size) {
  // ---- Robust input binding: identify tensors by element count, not position.
  int i1280=-1, i2048=-1, i225280=-1, i2816=-1, i256=-1;
  int i65536[2] = {-1,-1}; int n65536 = 0;
  int i720[3] = {-1,-1,-1}; int n720 = 0;
  for (int i=0;i<n_in;i++){
    switch (in_sizes[i]){
      case 1280:   i1280 = i; break;
      case 2048:   i2048 = i; break;
      case 225280: i225280 = i; break;
      case 2816:   i2816 = i; break;
      case 256:    i256 = i; break;
      case 65536:  if (n65536 < 2) i65536[n65536++] = i; break;
      case 720896: if (n720 < 3) i720[n720++] = i; break;
      default: break;
    }
  }
  if (i1280<0 || i2048<0 || i225280<0 || i2816<0 || i256<0 || n65536!=2 || n720!=3){
    i1280=0; i2048=1; i65536[0]=2; i225280=3; i720[0]=4; i720[1]=5; i720[2]=6;
    i2816=7; i65536[1]=8; i256=9;
  }
  const float* y        = (const float*)d_in[i1280];     // [80,16]
  const float* samples  = (const float*)d_in[i2048];     // [2048]
  const float* condW    = (const float*)d_in[i225280];   // [2816,80]
  const float* Wob      = (const float*)d_in[i2816];     // [11,256]
  const float* endb     = (const float*)d_in[i256];      // [256]
  const float* emb_raw  = (const float*)d_in[i65536[0]]; // [256,256]
  const float* endw     = (const float*)d_in[i65536[1]]; // [256,256]
  int before = 0;
  for (int k=0;k<3;k++) if (i720[k] < i2816) before++;
  const float *WVp, *WVc, *Wow;
  if (before == 0) { Wow = (const float*)d_in[i720[0]];
                     WVp = (const float*)d_in[i720[1]];
                     WVc = (const float*)d_in[i720[2]]; }
  else             { WVp = (const float*)d_in[i720[0]];
                     WVc = (const float*)d_in[i720[1]];
                     Wow = (const float*)d_in[i720[2]]; }
  float* out = (float*)d_out;                            // [2048] sampled ids (as float32)

  init_all<<<2048,256>>>(y, emb_raw, condW);

  cudaLaunchConfig_t cfg = {};
  cfg.gridDim  = dim3(NCTA,1,1);
  cfg.blockDim = dim3(512,1,1);
  int maxC = 0;
  cudaOccupancyMaxPotentialClusterSize(&maxC, fftnet_mbar, &cfg);  // pure query, capture-safe
  if (maxC >= NCTA)
    fftnet_mbar<<<NCTA,512>>>(WVp, WVc, Wow, Wob, endw, endb, samples, out);
  else
    fftnet_flags<<<NCTA,512>>>(WVp, WVc, Wow, Wob, endw, endb, samples, out);
}